// round 10
// baseline (speedup 1.0000x reference)
#include <cuda_runtime.h>
#include <cstdint>

#define H_IN   200
#define W_IN   320
#define C_IN   64
#define H_OUT  48
#define W_OUT  320

#define SRC_CH_STRIDE (H_IN * W_IN)    // 64000 floats
#define DST_CH_STRIDE (H_OUT * W_OUT)  // 15360 floats

#define QUADS       (W_OUT / 4)        // 80 column-quads per row
#define NTHREADS    320
#define CHUNK_ROWS  8                  // rows per staged chunk
#define NCHUNKS     (H_OUT / CHUNK_ROWS)          // 6
#define CHUNK_UNITS (CHUNK_ROWS * QUADS)          // 640 float4
#define CHUNK_BYTES (CHUNK_UNITS * 16)            // 10240

__global__ void __launch_bounds__(NTHREADS)
roi_crop_kernel(const float* __restrict__ x,
                const int*   __restrict__ bboxes,
                const int*   __restrict__ box_img,
                float*       __restrict__ out)
{
    const int c = blockIdx.x;    // channel 0..63
    const int b = blockIdx.y;    // box 0..255
    const int t = threadIdx.x;   // 0..319

    __shared__ int4 s_colq[QUADS];
    __shared__ int  s_row[H_OUT];
    __shared__ alignas(16) float4 sbuf[2][CHUNK_UNITS];   // 2 x 10240 B

    // bbox decode (uniform per block)
    int x0 = __ldg(&bboxes[b * 4 + 0]);
    int y0 = __ldg(&bboxes[b * 4 + 1]);
    int x1 = __ldg(&bboxes[b * 4 + 2]);
    int y1 = __ldg(&bboxes[b * 4 + 3]);
    x0 = min(max(x0, 0), W_IN - 1);
    y0 = min(max(y0, 0), H_IN - 1);
    x1 = min(max(x1, 0), W_IN - 1);
    y1 = min(max(y1, 0), H_IN - 1);
    x1 = max(x1, x0);
    y1 = max(y1, y0);
    const int h = y1 - y0 + 1;
    const int w = x1 - x0 + 1;

    if (t < QUADS) {
        const int j0 = t * 4;
        int4 cq;
        cq.x = x0 + ((j0 + 0) * w) / W_OUT;
        cq.y = x0 + ((j0 + 1) * w) / W_OUT;
        cq.z = x0 + ((j0 + 2) * w) / W_OUT;
        cq.w = x0 + ((j0 + 3) * w) / W_OUT;
        s_colq[t] = cq;
    }
    if (t >= 128 && t < 128 + H_OUT)
        s_row[t - 128] = y0 + ((t - 128) * h) / H_OUT;
    __syncthreads();

    const int img = __ldg(&box_img[b]);
    const float* __restrict__ src =
        x + (size_t)img * (C_IN * SRC_CH_STRIDE) + (size_t)c * SRC_CH_STRIDE;
    char* __restrict__ gdst =
        (char*)(out + ((size_t)b * C_IN + c) * DST_CH_STRIDE);

    for (int k = 0; k < NCHUNKS; k++) {
        const int buf = k & 1;

        // Buffer reuse: ensure the bulk store issued 2 chunks ago has drained.
        if (k >= 2) {
            if (t == 0)
                asm volatile("cp.async.bulk.wait_group 1;" ::: "memory");
            __syncthreads();
        }

        // Gather 640 float4 units (8 rows x 80 quads) into smem.
        #pragma unroll
        for (int it = 0; it < CHUNK_UNITS / NTHREADS; it++) {
            const int u  = it * NTHREADS + t;
            const int ri = u / QUADS;                 // row within chunk
            const int q  = u - ri * QUADS;
            const int4 cq = s_colq[q];
            const float* __restrict__ s =
                src + s_row[k * CHUNK_ROWS + ri] * W_IN;
            float4 v;
            v.x = __ldg(s + cq.x);
            v.y = __ldg(s + cq.y);
            v.z = __ldg(s + cq.z);
            v.w = __ldg(s + cq.w);
            sbuf[buf][u] = v;                          // STS.128, conflict-free
        }
        __syncthreads();

        // One thread issues the 10 KB bulk store (dense DRAM burst).
        if (t == 0) {
            uint32_t saddr;
            asm("{ .reg .u64 tmp; cvta.to.shared.u64 tmp, %1; cvt.u32.u64 %0, tmp; }"
                : "=r"(saddr) : "l"(&sbuf[buf][0]));
            asm volatile("fence.proxy.async.shared::cta;" ::: "memory");
            asm volatile(
                "cp.async.bulk.global.shared::cta.bulk_group [%0], [%1], %2;"
                :: "l"(gdst + (size_t)k * CHUNK_BYTES), "r"(saddr),
                   "n"(CHUNK_BYTES)
                : "memory");
            asm volatile("cp.async.bulk.commit_group;" ::: "memory");
        }
    }

    // Drain all outstanding bulk stores before exit.
    if (t == 0)
        asm volatile("cp.async.bulk.wait_group 0;" ::: "memory");
}

extern "C" void kernel_launch(void* const* d_in, const int* in_sizes, int n_in,
                              void* d_out, int out_size)
{
    const float* x       = (const float*)d_in[0];
    const int*   bboxes  = (const int*)d_in[1];
    const int*   box_img = (const int*)d_in[2];
    float*       out     = (float*)d_out;

    dim3 grid(C_IN, 256);                 // (64 channels, 256 boxes)
    roi_crop_kernel<<<grid, NTHREADS>>>(x, bboxes, box_img, out);
}

// round 11
// speedup vs baseline: 1.0772x; 1.0772x over previous
#include <cuda_runtime.h>

#define H_IN   200
#define W_IN   320
#define C_IN   64
#define H_OUT  48
#define W_OUT  320

#define SRC_CH_STRIDE (H_IN * W_IN)    // 64000 floats
#define DST_CH_STRIDE (H_OUT * W_OUT)  // 15360 floats

#define QUADS     (W_OUT / 4)          // 80 column-quads per row
#define NTHREADS  256
#define NUNITS    (H_OUT * QUADS)      // 3840 float4 units per (box,channel) tile

// minBlocksPerMultiprocessor=8 forces regs<=32 -> 2048 resident threads/SM
// (R7 compiled to 40 regs -> 6 CTAs/SM, occ 68%).
__global__ void __launch_bounds__(NTHREADS, 8)
roi_crop_kernel(const float* __restrict__ x,
                const int*   __restrict__ bboxes,
                const int*   __restrict__ box_img,
                float*       __restrict__ out)
{
    const int c = blockIdx.x;    // channel 0..63
    const int b = blockIdx.y;    // box 0..255
    const int t = threadIdx.x;   // 0..255

    __shared__ int4 s_colq[QUADS];   // 4 source cols per output quad
    __shared__ int  s_row[H_OUT];    // source row per output row

    // bbox decode (uniform per block)
    int x0 = __ldg(&bboxes[b * 4 + 0]);
    int y0 = __ldg(&bboxes[b * 4 + 1]);
    int x1 = __ldg(&bboxes[b * 4 + 2]);
    int y1 = __ldg(&bboxes[b * 4 + 3]);
    x0 = min(max(x0, 0), W_IN - 1);
    y0 = min(max(y0, 0), H_IN - 1);
    x1 = min(max(x1, 0), W_IN - 1);
    y1 = min(max(y1, 0), H_IN - 1);
    x1 = max(x1, x0);
    y1 = max(y1, y0);
    const int h = y1 - y0 + 1;
    const int w = x1 - x0 + 1;

    if (t < QUADS) {                         // 80 threads fill column quads
        const int j0 = t * 4;
        int4 cq;
        cq.x = x0 + ((j0 + 0) * w) / W_OUT;  // const-divisor -> mul/shift
        cq.y = x0 + ((j0 + 1) * w) / W_OUT;
        cq.z = x0 + ((j0 + 2) * w) / W_OUT;
        cq.w = x0 + ((j0 + 3) * w) / W_OUT;
        s_colq[t] = cq;
    }
    if (t >= 128 && t < 128 + H_OUT)         // 48 threads fill row map
        s_row[t - 128] = y0 + ((t - 128) * h) / H_OUT;
    __syncthreads();

    const int img = __ldg(&box_img[b]);
    const float* __restrict__ src =
        x + (size_t)img * (C_IN * SRC_CH_STRIDE) + (size_t)c * SRC_CH_STRIDE;
    // This block's output tile: 61440 bytes, written fully sequentially.
    float4* __restrict__ dst =
        (float4*)(out + ((size_t)b * C_IN + c) * DST_CH_STRIDE);

    // 3840 units / 256 threads = 15 iterations; consecutive threads write
    // consecutive float4s -> block-linear DRAM write stream.
    #pragma unroll 5
    for (int u = t; u < NUNITS; u += NTHREADS) {
        const int i = u / QUADS;             // output row
        const int q = u - i * QUADS;         // quad within row
        const int4 cq = s_colq[q];           // LDS.128, conflict-free
        const float* __restrict__ s = src + s_row[i] * W_IN;
        float4 v;
        v.x = __ldg(s + cq.x);
        v.y = __ldg(s + cq.y);
        v.z = __ldg(s + cq.z);
        v.w = __ldg(s + cq.w);
        dst[u] = v;
    }
}

extern "C" void kernel_launch(void* const* d_in, const int* in_sizes, int n_in,
                              void* d_out, int out_size)
{
    const float* x       = (const float*)d_in[0];
    const int*   bboxes  = (const int*)d_in[1];
    const int*   box_img = (const int*)d_in[2];
    float*       out     = (float*)d_out;

    dim3 grid(C_IN, 256);                 // (64 channels, 256 boxes)
    roi_crop_kernel<<<grid, NTHREADS>>>(x, bboxes, box_img, out);
}

// round 13
// speedup vs baseline: 1.1313x; 1.0502x over previous
#include <cuda_runtime.h>

#define H_IN   200
#define W_IN   320
#define C_IN   64
#define H_OUT  48
#define W_OUT  320

#define SRC_CH_STRIDE (H_IN * W_IN)    // 64000 floats
#define DST_CH_STRIDE (H_OUT * W_OUT)  // 15360 floats

#define QUADS     (W_OUT / 4)          // 80 column-quads per row
#define NTHREADS  256
#define NUNITS    (H_OUT * QUADS)      // 3840 float4 units per (box,channel) tile
#define NITERS    (NUNITS / NTHREADS)  // 15

__global__ void __launch_bounds__(NTHREADS)
roi_crop_kernel(const float* __restrict__ x,
                const int*   __restrict__ bboxes,
                const int*   __restrict__ box_img,
                float*       __restrict__ out)
{
    const int c = blockIdx.x;    // channel 0..63
    const int b = blockIdx.y;    // box 0..255
    const int t = threadIdx.x;   // 0..255

    __shared__ int4 s_colq[QUADS];   // 4 source cols per output quad
    __shared__ int  s_row[H_OUT];    // source row per output row

    // bbox decode (uniform per block)
    int x0 = __ldg(&bboxes[b * 4 + 0]);
    int y0 = __ldg(&bboxes[b * 4 + 1]);
    int x1 = __ldg(&bboxes[b * 4 + 2]);
    int y1 = __ldg(&bboxes[b * 4 + 3]);
    x0 = min(max(x0, 0), W_IN - 1);
    y0 = min(max(y0, 0), H_IN - 1);
    x1 = min(max(x1, 0), W_IN - 1);
    y1 = min(max(y1, 0), H_IN - 1);
    x1 = max(x1, x0);
    y1 = max(y1, y0);
    const int h = y1 - y0 + 1;
    const int w = x1 - x0 + 1;

    if (t < QUADS) {                         // 80 threads fill column quads
        const int j0 = t * 4;
        int4 cq;
        cq.x = x0 + ((j0 + 0) * w) / W_OUT;  // const-divisor -> mul/shift
        cq.y = x0 + ((j0 + 1) * w) / W_OUT;
        cq.z = x0 + ((j0 + 2) * w) / W_OUT;
        cq.w = x0 + ((j0 + 3) * w) / W_OUT;
        s_colq[t] = cq;
    }
    if (t >= 128 && t < 128 + H_OUT)         // 48 threads fill row map
        s_row[t - 128] = y0 + ((t - 128) * h) / H_OUT;
    __syncthreads();

    const int img = __ldg(&box_img[b]);
    const float* __restrict__ src =
        x + (size_t)img * (C_IN * SRC_CH_STRIDE) + (size_t)c * SRC_CH_STRIDE;
    // This block's output tile: 61440 bytes, written fully sequentially.
    float4* __restrict__ dst =
        (float4*)(out + ((size_t)b * C_IN + c) * DST_CH_STRIDE);

    // Software pipeline, depth 2: iteration m+1's gathers are issued before
    // iteration m's store, guaranteeing >=8 independent LDGs in flight per
    // thread. Write stream identical to the 170us kernel (block-linear).
    int u = t;
    int i = u / QUADS;
    int q = u - i * QUADS;
    int4 cq = s_colq[q];
    const float* s = src + s_row[i] * W_IN;
    float4 v;
    v.x = __ldg(s + cq.x);
    v.y = __ldg(s + cq.y);
    v.z = __ldg(s + cq.z);
    v.w = __ldg(s + cq.w);

    #pragma unroll
    for (int m = 0; m < NITERS - 1; m++) {
        const int un = u + NTHREADS;
        const int in = un / QUADS;
        const int qn = un - in * QUADS;
        const int4 cqn = s_colq[qn];
        const float* sn = src + s_row[in] * W_IN;
        float4 vn;
        vn.x = __ldg(sn + cqn.x);
        vn.y = __ldg(sn + cqn.y);
        vn.z = __ldg(sn + cqn.z);
        vn.w = __ldg(sn + cqn.w);

        dst[u] = v;          // store iteration m while m+1's loads are in flight
        v = vn;
        u = un;
    }
    dst[u] = v;
}

extern "C" void kernel_launch(void* const* d_in, const int* in_sizes, int n_in,
                              void* d_out, int out_size)
{
    const float* x       = (const float*)d_in[0];
    const int*   bboxes  = (const int*)d_in[1];
    const int*   box_img = (const int*)d_in[2];
    float*       out     = (float*)d_out;

    dim3 grid(C_IN, 256);                 // (64 channels, 256 boxes)
    roi_crop_kernel<<<grid, NTHREADS>>>(x, bboxes, box_img, out);
}